// round 8
// baseline (speedup 1.0000x reference)
#include <cuda_runtime.h>

// GCMConv: gauge-covariant convolution on 8x8x16x16 lattice.
// x: (1, 16384, 8, 3, 3, 2) float32  [channels: 4 gauge links U_a, 4 fields w_c]
// weight: (4, 9, 33) float32
// out: (1, 16384, 8, 3, 3, 2): [U (copied), w_out]
//
// M-form, scalar FFMA, 2-pass v-split:
//   M_v = sum_k c1_{vk} T_k + c2_{vk} T_k^dag  (+ c3_v I at epilogue)
//   w_out[u] = M_8 + sum_c w_c @ M_c + w_c^dag @ M_{4+c}
// Pass A: v in {0,1,2,3,8} (90-float M), pass B: v in {4..7} (72-float M).
// T streamed with prefetch depth 2 (ring of 3 buffers) to cover L2 latency.

#define NS 16384

// Scratch, float2 (re,im), [(e)*NS + site]:
//  e = k*9 + m        (k=0..15): T_k[m],  m = row*3+col
//  e = 144 + c*9 + m  (c=0..3) : own-site w_c[m]
__device__ float2 g_T[180 * NS];

__global__ __launch_bounds__(256) void transport_kernel(const float* __restrict__ x) {
    int g = blockIdx.x * 256 + threadIdx.x;   // 0 .. 4*NS-1
    int site = g & (NS - 1);
    int a = g >> 14;                           // axis 0..3

    // periodic +1 neighbor; dims (8,8,16,16), strides (2048,256,16,1)
    int d3 = site & 15, d2 = (site >> 4) & 15, d1 = (site >> 8) & 7, d0 = (site >> 11) & 7;
    int nbr;
    if (a == 0)      nbr = site + ((((d0 + 1) & 7) - d0) << 11);
    else if (a == 1) nbr = site + ((((d1 + 1) & 7) - d1) << 8);
    else if (a == 2) nbr = site + ((((d2 + 1) & 15) - d2) << 4);
    else             nbr = site + (((d3 + 1) & 15) - d3);

    float Ur[3][3], Ui[3][3];
    {
        const float2* up = (const float2*)(x + site * 144 + a * 18);
#pragma unroll
        for (int m = 0; m < 9; m++) {
            float2 t = up[m];
            Ur[m / 3][m % 3] = t.x;
            Ui[m / 3][m % 3] = t.y;
        }
    }

#pragma unroll
    for (int c = 0; c < 4; c++) {
        float Wr[3][3], Wi[3][3];
        const float2* wp = (const float2*)(x + nbr * 144 + (4 + c) * 18);
#pragma unroll
        for (int m = 0; m < 9; m++) {
            float2 t = wp[m];
            Wr[m / 3][m % 3] = t.x;
            Wi[m / 3][m % 3] = t.y;
        }
        // t1 = U @ W
        float t1r[3][3], t1i[3][3];
#pragma unroll
        for (int i = 0; i < 3; i++)
#pragma unroll
            for (int kk = 0; kk < 3; kk++) {
                float cr = 0.f, ci = 0.f;
#pragma unroll
                for (int j = 0; j < 3; j++) {
                    cr += Ur[i][j] * Wr[j][kk] - Ui[i][j] * Wi[j][kk];
                    ci += Ur[i][j] * Wi[j][kk] + Ui[i][j] * Wr[j][kk];
                }
                t1r[i][kk] = cr;
                t1i[i][kk] = ci;
            }
        // T = t1 @ U^dag
        int ebase = (a * 4 + c) * 9;
#pragma unroll
        for (int i = 0; i < 3; i++)
#pragma unroll
            for (int kk = 0; kk < 3; kk++) {
                float cr = 0.f, ci = 0.f;
#pragma unroll
                for (int j = 0; j < 3; j++) {
                    float br = Ur[kk][j], bi = -Ui[kk][j];
                    cr += t1r[i][j] * br - t1i[i][j] * bi;
                    ci += t1r[i][j] * bi + t1i[i][j] * br;
                }
                g_T[(ebase + i * 3 + kk) * NS + site] = make_float2(cr, ci);
            }
    }

    // own-site field: thread (site, a) copies channel c = a
    {
        const float2* wp = (const float2*)(x + site * 144 + (4 + a) * 18);
#pragma unroll
        for (int m = 0; m < 9; m++)
            g_T[(144 + a * 9 + m) * NS + site] = wp[m];
    }
}

__global__ __launch_bounds__(128, 3) void contract_kernel(const float* __restrict__ x,
                                                          const float* __restrict__ weight,
                                                          float* __restrict__ out) {
    __shared__ float wt[297];   // [w*9 + v] = weight[u, v, w]

    int g = blockIdx.x * 128 + threadIdx.x;
    int site = g & (NS - 1);
    int u = g >> 14;  // whole block shares one u

    for (int s = threadIdx.x; s < 297; s += 128) {
        int v = s / 33, w = s % 33;
        wt[w * 9 + v] = weight[u * 297 + s];
    }
    __syncthreads();

    // copy gauge link channel u to output
    {
        const float2* src = (const float2*)(x + site * 144 + u * 18);
        float2* dst = (float2*)(out + site * 144 + u * 18);
#pragma unroll
        for (int m = 0; m < 9; m++) dst[m] = src[m];
    }

    float accr[3][3], acci[3][3];

    // ================= Pass A: v in {0,1,2,3,8} =================
    {
        float Mr[5][9], Mi[5][9];
#pragma unroll
        for (int t = 0; t < 5; t++)
#pragma unroll
            for (int m = 0; m < 9; m++) { Mr[t][m] = 0.f; Mi[t][m] = 0.f; }

        float2 Tb[3][9];
#pragma unroll
        for (int m = 0; m < 9; m++) Tb[0][m] = g_T[m * NS + site];
#pragma unroll
        for (int m = 0; m < 9; m++) Tb[1][m] = g_T[(9 + m) * NS + site];

#pragma unroll
        for (int k = 0; k < 16; k++) {
            const int cur = k % 3;
            if (k < 14) {
                const int nxt = (k + 2) % 3;
#pragma unroll
                for (int m = 0; m < 9; m++)
                    Tb[nxt][m] = g_T[((k + 2) * 9 + m) * NS + site];
            }
#pragma unroll
            for (int t = 0; t < 5; t++) {
                const int v = (t < 4) ? t : 8;
                float c1 = wt[k * 9 + v];
                float c2 = wt[(16 + k) * 9 + v];
#pragma unroll
                for (int i = 0; i < 3; i++)
#pragma unroll
                    for (int j = 0; j < 3; j++) {
                        Mr[t][i * 3 + j] += c1 * Tb[cur][i * 3 + j].x + c2 * Tb[cur][j * 3 + i].x;
                        Mi[t][i * 3 + j] += c1 * Tb[cur][i * 3 + j].y - c2 * Tb[cur][j * 3 + i].y;
                    }
            }
        }

        // acc = M_8 + c3_8 I
        {
            float c3 = wt[288 + 8];
#pragma unroll
            for (int i = 0; i < 3; i++)
#pragma unroll
                for (int j = 0; j < 3; j++) {
                    accr[i][j] = Mr[4][i * 3 + j] + ((i == j) ? c3 : 0.f);
                    acci[i][j] = Mi[4][i * 3 + j];
                }
        }

        // acc += w_c @ (M_c + c3_c I)
#pragma unroll
        for (int c = 0; c < 4; c++) {
            float c3 = wt[288 + c];
            float nr[3][3], ni[3][3];
#pragma unroll
            for (int i = 0; i < 3; i++)
#pragma unroll
                for (int j = 0; j < 3; j++) {
                    nr[i][j] = Mr[c][i * 3 + j] + ((i == j) ? c3 : 0.f);
                    ni[i][j] = Mi[c][i * 3 + j];
                }
            float wr[3][3], wi[3][3];
#pragma unroll
            for (int m = 0; m < 9; m++) {
                float2 t2 = g_T[(144 + c * 9 + m) * NS + site];
                wr[m / 3][m % 3] = t2.x;
                wi[m / 3][m % 3] = t2.y;
            }
#pragma unroll
            for (int i = 0; i < 3; i++)
#pragma unroll
                for (int kk = 0; kk < 3; kk++) {
                    float cr = accr[i][kk], ci = acci[i][kk];
#pragma unroll
                    for (int j = 0; j < 3; j++) {
                        cr += wr[i][j] * nr[j][kk] - wi[i][j] * ni[j][kk];
                        ci += wr[i][j] * ni[j][kk] + wi[i][j] * nr[j][kk];
                    }
                    accr[i][kk] = cr; acci[i][kk] = ci;
                }
        }
    }

    // ================= Pass B: v in {4,5,6,7} =================
    {
        float Mr[4][9], Mi[4][9];
#pragma unroll
        for (int t = 0; t < 4; t++)
#pragma unroll
            for (int m = 0; m < 9; m++) { Mr[t][m] = 0.f; Mi[t][m] = 0.f; }

        float2 Tb[3][9];
#pragma unroll
        for (int m = 0; m < 9; m++) Tb[0][m] = g_T[m * NS + site];
#pragma unroll
        for (int m = 0; m < 9; m++) Tb[1][m] = g_T[(9 + m) * NS + site];

#pragma unroll
        for (int k = 0; k < 16; k++) {
            const int cur = k % 3;
            if (k < 14) {
                const int nxt = (k + 2) % 3;
#pragma unroll
                for (int m = 0; m < 9; m++)
                    Tb[nxt][m] = g_T[((k + 2) * 9 + m) * NS + site];
            }
#pragma unroll
            for (int t = 0; t < 4; t++) {
                const int v = 4 + t;
                float c1 = wt[k * 9 + v];
                float c2 = wt[(16 + k) * 9 + v];
#pragma unroll
                for (int i = 0; i < 3; i++)
#pragma unroll
                    for (int j = 0; j < 3; j++) {
                        Mr[t][i * 3 + j] += c1 * Tb[cur][i * 3 + j].x + c2 * Tb[cur][j * 3 + i].x;
                        Mi[t][i * 3 + j] += c1 * Tb[cur][i * 3 + j].y - c2 * Tb[cur][j * 3 + i].y;
                    }
            }
        }

        // acc += w_c^dag @ (M_{4+c} + c3 I) : conj(w[j][i]) * N[j][kk]
#pragma unroll
        for (int c = 0; c < 4; c++) {
            float c3 = wt[288 + 4 + c];
            float nr[3][3], ni[3][3];
#pragma unroll
            for (int i = 0; i < 3; i++)
#pragma unroll
                for (int j = 0; j < 3; j++) {
                    nr[i][j] = Mr[c][i * 3 + j] + ((i == j) ? c3 : 0.f);
                    ni[i][j] = Mi[c][i * 3 + j];
                }
            float wr[3][3], wi[3][3];
#pragma unroll
            for (int m = 0; m < 9; m++) {
                float2 t2 = g_T[(144 + c * 9 + m) * NS + site];
                wr[m / 3][m % 3] = t2.x;
                wi[m / 3][m % 3] = t2.y;
            }
#pragma unroll
            for (int i = 0; i < 3; i++)
#pragma unroll
                for (int kk = 0; kk < 3; kk++) {
                    float cr = accr[i][kk], ci = acci[i][kk];
#pragma unroll
                    for (int j = 0; j < 3; j++) {
                        cr += wr[j][i] * nr[j][kk] + wi[j][i] * ni[j][kk];
                        ci += wr[j][i] * ni[j][kk] - wi[j][i] * nr[j][kk];
                    }
                    accr[i][kk] = cr; acci[i][kk] = ci;
                }
        }
    }

    float2* dst = (float2*)(out + site * 144 + (4 + u) * 18);
#pragma unroll
    for (int i = 0; i < 3; i++)
#pragma unroll
        for (int j = 0; j < 3; j++)
            dst[i * 3 + j] = make_float2(accr[i][j], acci[i][j]);
}

extern "C" void kernel_launch(void* const* d_in, const int* in_sizes, int n_in,
                              void* d_out, int out_size) {
    const float* x = (const float*)d_in[0];
    const float* weight = (const float*)d_in[1];
    float* out = (float*)d_out;

    transport_kernel<<<4 * NS / 256, 256>>>(x);
    contract_kernel<<<4 * NS / 128, 128>>>(x, weight, out);
}